// round 10
// baseline (speedup 1.0000x reference)
#include <cuda_runtime.h>

#define NX 4096
#define NY 4096
#define DT    5e-4f
#define INV2  500.0f          // 1/(2*dx) = 1/(2*dy)
#define DTI   (DT * INV2)     // 0.25
#define TY    16              // tile rows per block

__device__ __forceinline__ float4 ld4(const float* __restrict__ p) {
    return __ldg(reinterpret_cast<const float4*>(p));
}

__device__ __forceinline__ float frcp(float x) {
    float r;
    asm("rcp.approx.f32 %0, %1;" : "=f"(r) : "f"(x));
    return r;
}

__device__ __forceinline__ float lane(const float4& v, int l) {
    return (l == 0) ? v.x : (l == 1) ? v.y : (l == 2) ? v.z : v.w;
}
__device__ __forceinline__ void setlane(float4& v, int l, float f) {
    if      (l == 0) v.x = f;
    else if (l == 1) v.y = f;
    else if (l == 2) v.z = f;
    else             v.w = f;
}

template<bool EDGE>
__device__ __forceinline__ void fdtd_tile(
    const float* __restrict__ Ez,
    const float* __restrict__ Hx,
    const float* __restrict__ Hy,
    const float* __restrict__ eps,
    const float* __restrict__ mu,
    const float* __restrict__ sig,
    float* __restrict__ oez,
    float* __restrict__ ohx,
    float* __restrict__ ohy,
    float4 (*s_hyn)[32])
{
    const int tx = threadIdx.x;                 // 0..31 (vec4 col) == lane id
    const int ty = threadIdx.y;                 // 0..TY-1 (row) — one warp per row
    const int j0 = (blockIdx.x * 32 + tx) << 2;
    const int i  = blockIdx.y * TY + ty;
    const int base = i * NY + j0;

    const float4 z4   = make_float4(0.f, 0.f, 0.f, 0.f);
    const float4 one4 = make_float4(1.f, 1.f, 1.f, 1.f);

    const float m_int_i = (!EDGE || (i >= 1 && i <= NX - 2)) ? 1.0f : 0.0f;
    const bool  has_im1 = !EDGE || (i >= 1);
    const bool  has_ip1 = !EDGE || (i <= NX - 2);

    // ---- main loads (no j-halo loads: those come via shuffle) ----
    const float4 ez_c  = ld4(Ez + base);
    const float4 ez_m1 = has_im1 ? ld4(Ez + base - NY) : z4;
    const float4 ez_p1 = has_ip1 ? ld4(Ez + base + NY) : z4;
    const float4 hx_c  = ld4(Hx + base);
    const float4 hy_c  = ld4(Hy + base);
    const float4 mu_c  = ld4(mu + base);
    const float4 ep4   = ld4(eps + base);
    const float4 sg4   = ld4(sig + base);

    // ---- halo rows: warp 0 -> tile_top-1, warp TY-1 -> tile_top+TY ----
    if (ty == 0) {
        const int  ih  = i - 1;
        const bool hv  = !EDGE || (ih >= 0);
        const int  hb  = ih * NY + j0;
        const float4 hy_h  = hv ? ld4(Hy + hb) : z4;
        const float4 mu_h  = hv ? ld4(mu + hb) : one4;
        const float4 ez_mm = (!EDGE || ih >= 1) ? ld4(Ez + hb - NY) : z4;
        const float m_h = (!EDGE || (ih >= 1 && ih <= NX - 2)) ? 1.0f : 0.0f;
        float4 hyn_h;   // ez(ih+1) == ez_c
#pragma unroll
        for (int l = 0; l < 4; ++l) {
            const int   j   = j0 + l;
            const float m_j = (!EDGE || (j >= 1 && j <= NY - 2)) ? 1.0f : 0.0f;
            const float d   = (lane(ez_c, l) - lane(ez_mm, l)) * (m_h * m_j);
            setlane(hyn_h, l, lane(hy_h, l) + DTI * d * frcp(lane(mu_h, l)));
        }
        s_hyn[0][tx] = hyn_h;
    }
    if (ty == TY - 1) {
        const int  ih  = i + 1;
        const bool hv  = !EDGE || (ih <= NX - 1);
        const int  hb  = ih * NY + j0;
        const float4 hy_h  = hv ? ld4(Hy + hb) : z4;
        const float4 mu_h  = hv ? ld4(mu + hb) : one4;
        const float4 ez_pp = (!EDGE || ih <= NX - 2) ? ld4(Ez + hb + NY) : z4;
        const float m_h = (!EDGE || (ih >= 1 && ih <= NX - 2)) ? 1.0f : 0.0f;
        float4 hyn_h;   // ez(ih-1) == ez_c
#pragma unroll
        for (int l = 0; l < 4; ++l) {
            const int   j   = j0 + l;
            const float m_j = (!EDGE || (j >= 1 && j <= NY - 2)) ? 1.0f : 0.0f;
            const float d   = (lane(ez_pp, l) - lane(ez_c, l)) * (m_h * m_j);
            setlane(hyn_h, l, lane(hy_h, l) + DTI * d * frcp(lane(mu_h, l)));
        }
        s_hyn[TY + 1][tx] = hyn_h;
    }

    const float4 rmu4 = make_float4(frcp(mu_c.x), frcp(mu_c.y),
                                    frcp(mu_c.z), frcp(mu_c.w));

    // ---- j-halo via warp shuffle; lanes 0/31 fix up from global ----
    const unsigned FULL = 0xFFFFFFFFu;
    float ez_lz = __shfl_up_sync  (FULL, ez_c.z, 1);   // col j0-2
    float ez_lw = __shfl_up_sync  (FULL, ez_c.w, 1);   // col j0-1
    float ez_rx = __shfl_down_sync(FULL, ez_c.x, 1);   // col j0+4
    float ez_ry = __shfl_down_sync(FULL, ez_c.y, 1);   // col j0+5
    float hx_l  = __shfl_up_sync  (FULL, hx_c.w, 1);   // col j0-1
    float hx_r  = __shfl_down_sync(FULL, hx_c.x, 1);   // col j0+4
    float rmu_l = __shfl_up_sync  (FULL, rmu4.w, 1);   // col j0-1
    float rmu_r = __shfl_down_sync(FULL, rmu4.x, 1);   // col j0+4

    if (tx == 0) {
        if (!EDGE || j0 > 0) {
            ez_lz = __ldg(Ez + base - 2);
            ez_lw = __ldg(Ez + base - 1);
            hx_l  = __ldg(Hx + base - 1);
            rmu_l = frcp(__ldg(mu + base - 1));
        } else {
            ez_lz = 0.f; ez_lw = 0.f; hx_l = 0.f; rmu_l = 1.f;
        }
    }
    if (tx == 31) {
        if (!EDGE || j0 + 4 < NY) {
            ez_rx = __ldg(Ez + base + 4);
            ez_ry = __ldg(Ez + base + 5);
            hx_r  = __ldg(Hx + base + 4);
            rmu_r = frcp(__ldg(mu + base + 4));
        } else {
            ez_rx = 0.f; ez_ry = 0.f; hx_r = 0.f; rmu_r = 1.f;
        }
    }

    const float ezr[8]  = {ez_lz, ez_lw, ez_c.x, ez_c.y,
                           ez_c.z, ez_c.w, ez_rx, ez_ry};
    const float hxr[6]  = {hx_l, hx_c.x, hx_c.y, hx_c.z, hx_c.w, hx_r};
    const float rmur[6] = {rmu_l, rmu4.x, rmu4.y, rmu4.z, rmu4.w, rmu_r};

    // ---- phase 1: own H update ----
    float4 out_hx4, out_hy4;
#pragma unroll
    for (int l = 0; l < 4; ++l) {
        const int   j   = j0 + l;
        const float m_j = (!EDGE || (j >= 1 && j <= NY - 2)) ? 1.0f : 0.0f;
        const float m   = m_int_i * m_j;
        const float rmu = rmur[l + 1];
        const float ddy = (ezr[l + 3] - ezr[l + 1]) * m;
        const float ddx = (lane(ez_p1, l) - lane(ez_m1, l)) * m;
        setlane(out_hx4, l, hxr[l + 1] - DTI * ddy * rmu);
        setlane(out_hy4, l, lane(hy_c, l) + DTI * ddx * rmu);
    }
    *reinterpret_cast<float4*>(ohx + base) = out_hx4;
    *reinterpret_cast<float4*>(ohy + base) = out_hy4;
    s_hyn[ty + 1][tx] = out_hy4;

    __syncthreads();

    // ---- phase 2: Ez update using exchanged hyn ----
    const float4 hyn_p4 = s_hyn[ty + 2][tx];   // row i+1
    const float4 hyn_m4 = s_hyn[ty][tx];       // row i-1

    float4 out_ez4;
#pragma unroll
    for (int l = 0; l < 4; ++l) {
        const int   j     = j0 + l;
        const float m_j   = (!EDGE || (j >= 1 && j <= NY - 2)) ? 1.0f : 0.0f;
        const float m_int = m_int_i * m_j;
        const float ezc   = ezr[l + 2];

        // (A-/A+) = (eps-c)/(eps+c), DT/(A+ eps) = DT/(eps+c), c = 0.5*DT*sig
        const float e    = lane(ep4, l);
        const float c    = (0.5f * DT) * lane(sg4, l);
        const float rden = frcp(e + c);
        float ezn = (e - c) * rden * ezc;

        const float mjp  = (!EDGE || (j + 1 <= NY - 2)) ? 1.0f : 0.0f;
        const float djp  = (ezr[l + 4] - ezc) * mjp;
        const float hxnp = hxr[l + 2] - DTI * djp * rmur[l + 2];
        const float mjm  = (!EDGE || (j >= 2)) ? 1.0f : 0.0f;
        const float djm  = (ezc - ezr[l]) * mjm;
        const float hxnm = hxr[l] - DTI * djm * rmur[l];

        const float curl = (lane(hyn_p4, l) - lane(hyn_m4, l)
                            - hxnp + hxnm) * INV2;
        ezn += (DT * rden) * curl * m_int;
        setlane(out_ez4, l, ezn);
    }
    *reinterpret_cast<float4*>(oez + base) = out_ez4;
}

__global__ __launch_bounds__(32 * TY, 2) void fdtd_smem_kernel(
    const float* __restrict__ Ez,
    const float* __restrict__ Hx,
    const float* __restrict__ Hy,
    const float* __restrict__ eps,
    const float* __restrict__ mu,
    const float* __restrict__ sig,
    float* __restrict__ oez,
    float* __restrict__ ohx,
    float* __restrict__ ohy)
{
    __shared__ float4 s_hyn[TY + 2][32];

    const bool edge = (blockIdx.x == 0) | (blockIdx.x == gridDim.x - 1) |
                      (blockIdx.y == 0) | (blockIdx.y == gridDim.y - 1);

    if (edge) {
        fdtd_tile<true >(Ez, Hx, Hy, eps, mu, sig, oez, ohx, ohy, s_hyn);
    } else {
        fdtd_tile<false>(Ez, Hx, Hy, eps, mu, sig, oez, ohx, ohy, s_hyn);
    }
}

extern "C" void kernel_launch(void* const* d_in, const int* in_sizes, int n_in,
                              void* d_out, int out_size)
{
    const float* Ez  = (const float*)d_in[0];
    const float* Hx  = (const float*)d_in[1];
    const float* Hy  = (const float*)d_in[2];
    const float* eps = (const float*)d_in[3];
    const float* mu  = (const float*)d_in[4];
    const float* sig = (const float*)d_in[5];

    float* out = (float*)d_out;
    const int N = NX * NY;

    dim3 block(32, TY);                // 128 cols (vec4) x TY rows per block
    dim3 grid(NY / 128, NX / TY);      // (32, 256)
    fdtd_smem_kernel<<<grid, block>>>(Ez, Hx, Hy, eps, mu, sig,
                                      out, out + N, out + 2 * N);
}

// round 11
// speedup vs baseline: 1.0706x; 1.0706x over previous
#include <cuda_runtime.h>

#define NX 4096
#define NY 4096
#define DT    5e-4f
#define INV2  500.0f          // 1/(2*dx) = 1/(2*dy)
#define DTI   (DT * INV2)     // 0.25
#define TROWS 16              // tile rows per block (2 per warp, 8 warps)

__device__ __forceinline__ float4 ld4(const float* __restrict__ p) {
    return __ldg(reinterpret_cast<const float4*>(p));
}

__device__ __forceinline__ float frcp(float x) {
    float r;
    asm("rcp.approx.f32 %0, %1;" : "=f"(r) : "f"(x));
    return r;
}

__device__ __forceinline__ float lane(const float4& v, int l) {
    return (l == 0) ? v.x : (l == 1) ? v.y : (l == 2) ? v.z : v.w;
}
__device__ __forceinline__ void setlane(float4& v, int l, float f) {
    if      (l == 0) v.x = f;
    else if (l == 1) v.y = f;
    else if (l == 2) v.z = f;
    else             v.w = f;
}

template<bool EDGE>
__device__ __forceinline__ void fdtd_tile(
    const float* __restrict__ Ez,
    const float* __restrict__ Hx,
    const float* __restrict__ Hy,
    const float* __restrict__ eps,
    const float* __restrict__ mu,
    const float* __restrict__ sig,
    float* __restrict__ oez,
    float* __restrict__ ohx,
    float* __restrict__ ohy,
    float4 (*s_hyn)[32])
{
    const int tx = threadIdx.x;                 // 0..31 (vec4 col)
    const int ty = threadIdx.y;                 // 0..7 — one warp per ROW PAIR
    const int j0 = (blockIdx.x * 32 + tx) << 2;
    const int i0 = blockIdx.y * TROWS + 2 * ty; // even row of the pair
    const int i1 = i0 + 1;                      // odd row
    const int b0 = i0 * NY + j0;
    const int b1 = b0 + NY;

    const float4 z4   = make_float4(0.f, 0.f, 0.f, 0.f);
    const float4 one4 = make_float4(1.f, 1.f, 1.f, 1.f);

    // i0 is even: i0 <= NX-2 always; i1 is odd: i1 >= 1 always.
    const float m_i0 = (!EDGE || (i0 >= 1))      ? 1.0f : 0.0f;
    const float m_i1 = (!EDGE || (i1 <= NX - 2)) ? 1.0f : 0.0f;
    const bool  jlo  = !EDGE || (j0 > 0);
    const bool  jhi  = !EDGE || (j0 + 4 < NY);

    // ---- loads: both rows of the pair ----
    const float4 ez_c0 = ld4(Ez + b0);
    const float4 ez_c1 = ld4(Ez + b1);
    const float4 ez_l0 = jlo ? ld4(Ez + b0 - 4) : z4;
    const float4 ez_r0 = jhi ? ld4(Ez + b0 + 4) : z4;
    const float4 ez_l1 = jlo ? ld4(Ez + b1 - 4) : z4;
    const float4 ez_r1 = jhi ? ld4(Ez + b1 + 4) : z4;
    const float4 ez_m1 = (!EDGE || i0 >= 1)      ? ld4(Ez + b0 - NY) : z4; // row i0-1
    const float4 ez_p1 = (!EDGE || i1 <= NX - 2) ? ld4(Ez + b1 + NY) : z4; // row i1+1

    const float4 hx_c0 = ld4(Hx + b0);
    const float4 hx_l0 = jlo ? ld4(Hx + b0 - 4) : z4;
    const float4 hx_r0 = jhi ? ld4(Hx + b0 + 4) : z4;
    const float4 hx_c1 = ld4(Hx + b1);
    const float4 hx_l1 = jlo ? ld4(Hx + b1 - 4) : z4;
    const float4 hx_r1 = jhi ? ld4(Hx + b1 + 4) : z4;

    const float4 hy_c0 = ld4(Hy + b0);
    const float4 hy_c1 = ld4(Hy + b1);

    const float4 mu_c0 = ld4(mu + b0);
    const float4 mu_l0 = jlo ? ld4(mu + b0 - 4) : one4;
    const float4 mu_r0 = jhi ? ld4(mu + b0 + 4) : one4;
    const float4 mu_c1 = ld4(mu + b1);
    const float4 mu_l1 = jlo ? ld4(mu + b1 - 4) : one4;
    const float4 mu_r1 = jhi ? ld4(mu + b1 + 4) : one4;

    // ---- halo rows ----
    if (ty == 0) {  // row I0-1 -> s_hyn[0];  ez(ih+1) == ez_c0
        const int  ih = i0 - 1;
        const bool hv = !EDGE || (ih >= 0);
        const int  hb = ih * NY + j0;
        const float4 hy_h  = hv ? ld4(Hy + hb) : z4;
        const float4 mu_h  = hv ? ld4(mu + hb) : one4;
        const float4 ez_mm = (!EDGE || ih >= 1) ? ld4(Ez + hb - NY) : z4;
        const float m_h = (!EDGE || (ih >= 1)) ? 1.0f : 0.0f;
        float4 hyn_h;
#pragma unroll
        for (int l = 0; l < 4; ++l) {
            const int   j   = j0 + l;
            const float m_j = (!EDGE || (j >= 1 && j <= NY - 2)) ? 1.0f : 0.0f;
            const float d   = (lane(ez_c0, l) - lane(ez_mm, l)) * (m_h * m_j);
            setlane(hyn_h, l, lane(hy_h, l) + DTI * d * frcp(lane(mu_h, l)));
        }
        s_hyn[0][tx] = hyn_h;
    }
    if (ty == 7) {  // row I0+16 -> s_hyn[17];  ez(ih-1) == ez_c1
        const int  ih = i1 + 1;
        const bool hv = !EDGE || (ih <= NX - 1);
        const int  hb = ih * NY + j0;
        const float4 hy_h  = hv ? ld4(Hy + hb) : z4;
        const float4 mu_h  = hv ? ld4(mu + hb) : one4;
        const float4 ez_pp = (!EDGE || ih <= NX - 2) ? ld4(Ez + hb + NY) : z4;
        const float m_h = (!EDGE || (ih <= NX - 2)) ? 1.0f : 0.0f;
        float4 hyn_h;
#pragma unroll
        for (int l = 0; l < 4; ++l) {
            const int   j   = j0 + l;
            const float m_j = (!EDGE || (j >= 1 && j <= NY - 2)) ? 1.0f : 0.0f;
            const float d   = (lane(ez_pp, l) - lane(ez_c1, l)) * (m_h * m_j);
            setlane(hyn_h, l, lane(hy_h, l) + DTI * d * frcp(lane(mu_h, l)));
        }
        s_hyn[TROWS + 1][tx] = hyn_h;
    }

    const float4 rmu0 = make_float4(frcp(mu_c0.x), frcp(mu_c0.y),
                                    frcp(mu_c0.z), frcp(mu_c0.w));
    const float4 rmu1 = make_float4(frcp(mu_c1.x), frcp(mu_c1.y),
                                    frcp(mu_c1.z), frcp(mu_c1.w));

    const float ezr0[8]  = {ez_l0.z, ez_l0.w, ez_c0.x, ez_c0.y,
                            ez_c0.z, ez_c0.w, ez_r0.x, ez_r0.y};
    const float ezr1[8]  = {ez_l1.z, ez_l1.w, ez_c1.x, ez_c1.y,
                            ez_c1.z, ez_c1.w, ez_r1.x, ez_r1.y};
    const float hxr0[6]  = {hx_l0.w, hx_c0.x, hx_c0.y, hx_c0.z, hx_c0.w, hx_r0.x};
    const float hxr1[6]  = {hx_l1.w, hx_c1.x, hx_c1.y, hx_c1.z, hx_c1.w, hx_r1.x};
    const float rmur0[6] = {frcp(mu_l0.w), rmu0.x, rmu0.y, rmu0.z, rmu0.w, frcp(mu_r0.x)};
    const float rmur1[6] = {frcp(mu_l1.w), rmu1.x, rmu1.y, rmu1.z, rmu1.w, frcp(mu_r1.x)};

    // ---- phase 1: H updates for both rows ----
    float4 hxn0, hyn0, hxn1, hyn1;
#pragma unroll
    for (int l = 0; l < 4; ++l) {
        const int   j   = j0 + l;
        const float m_j = (!EDGE || (j >= 1 && j <= NY - 2)) ? 1.0f : 0.0f;
        const float m0  = m_i0 * m_j;
        const float m1  = m_i1 * m_j;
        // row i0:  ddx uses ez(i1) - ez(i0-1)
        const float ddy0 = (ezr0[l + 3] - ezr0[l + 1]) * m0;
        const float ddx0 = (lane(ez_c1, l) - lane(ez_m1, l)) * m0;
        setlane(hxn0, l, hxr0[l + 1] - DTI * ddy0 * rmur0[l + 1]);
        setlane(hyn0, l, lane(hy_c0, l) + DTI * ddx0 * rmur0[l + 1]);
        // row i1:  ddx uses ez(i1+1) - ez(i0)
        const float ddy1 = (ezr1[l + 3] - ezr1[l + 1]) * m1;
        const float ddx1 = (lane(ez_p1, l) - lane(ez_c0, l)) * m1;
        setlane(hxn1, l, hxr1[l + 1] - DTI * ddy1 * rmur1[l + 1]);
        setlane(hyn1, l, lane(hy_c1, l) + DTI * ddx1 * rmur1[l + 1]);
    }
    *reinterpret_cast<float4*>(ohx + b0) = hxn0;
    *reinterpret_cast<float4*>(ohy + b0) = hyn0;
    *reinterpret_cast<float4*>(ohx + b1) = hxn1;
    *reinterpret_cast<float4*>(ohy + b1) = hyn1;
    s_hyn[1 + 2 * ty][tx] = hyn0;
    s_hyn[2 + 2 * ty][tx] = hyn1;

    // eps/sig issued here: latency overlaps the barrier
    const float4 ep0 = ld4(eps + b0);
    const float4 ep1 = ld4(eps + b1);
    const float4 sg0 = ld4(sig + b0);
    const float4 sg1 = ld4(sig + b1);

    __syncthreads();

    // ---- phase 2: Ez updates ----
    const float4 hyn_m0 = s_hyn[2 * ty][tx];      // row i0-1 (cross-warp)
    const float4 hyn_p1 = s_hyn[3 + 2 * ty][tx];  // row i1+1 (cross-warp)
    // row i0's +1 neighbor is hyn1 (register); row i1's -1 neighbor is hyn0.

    float4 oez0, oez1;
#pragma unroll
    for (int l = 0; l < 4; ++l) {
        const int   j    = j0 + l;
        const float m_j  = (!EDGE || (j >= 1 && j <= NY - 2)) ? 1.0f : 0.0f;
        const float mjp  = (!EDGE || (j + 1 <= NY - 2)) ? 1.0f : 0.0f;
        const float mjm  = (!EDGE || (j >= 2)) ? 1.0f : 0.0f;

        // --- row i0 ---
        {
            const float m_int = m_i0 * m_j;
            const float ezc   = ezr0[l + 2];
            const float e     = lane(ep0, l);
            const float c     = (0.5f * DT) * lane(sg0, l);
            const float rden  = frcp(e + c);
            float ezn = (e - c) * rden * ezc;

            const float djp  = (ezr0[l + 4] - ezc) * mjp;
            const float hxnp = hxr0[l + 2] - DTI * djp * rmur0[l + 2];
            const float djm  = (ezc - ezr0[l]) * mjm;
            const float hxnm = hxr0[l] - DTI * djm * rmur0[l];

            const float curl = (lane(hyn1, l) - lane(hyn_m0, l)
                                - hxnp + hxnm) * INV2;
            ezn += (DT * rden) * curl * m_int;
            setlane(oez0, l, ezn);
        }
        // --- row i1 ---
        {
            const float m_int = m_i1 * m_j;
            const float ezc   = ezr1[l + 2];
            const float e     = lane(ep1, l);
            const float c     = (0.5f * DT) * lane(sg1, l);
            const float rden  = frcp(e + c);
            float ezn = (e - c) * rden * ezc;

            const float djp  = (ezr1[l + 4] - ezc) * mjp;
            const float hxnp = hxr1[l + 2] - DTI * djp * rmur1[l + 2];
            const float djm  = (ezc - ezr1[l]) * mjm;
            const float hxnm = hxr1[l] - DTI * djm * rmur1[l];

            const float curl = (lane(hyn_p1, l) - lane(hyn0, l)
                                - hxnp + hxnm) * INV2;
            ezn += (DT * rden) * curl * m_int;
            setlane(oez1, l, ezn);
        }
    }
    *reinterpret_cast<float4*>(oez + b0) = oez0;
    *reinterpret_cast<float4*>(oez + b1) = oez1;
}

__global__ __launch_bounds__(256, 3) void fdtd_pair_kernel(
    const float* __restrict__ Ez,
    const float* __restrict__ Hx,
    const float* __restrict__ Hy,
    const float* __restrict__ eps,
    const float* __restrict__ mu,
    const float* __restrict__ sig,
    float* __restrict__ oez,
    float* __restrict__ ohx,
    float* __restrict__ ohy)
{
    __shared__ float4 s_hyn[TROWS + 2][32];

    const bool edge = (blockIdx.x == 0) | (blockIdx.x == gridDim.x - 1) |
                      (blockIdx.y == 0) | (blockIdx.y == gridDim.y - 1);

    if (edge) {
        fdtd_tile<true >(Ez, Hx, Hy, eps, mu, sig, oez, ohx, ohy, s_hyn);
    } else {
        fdtd_tile<false>(Ez, Hx, Hy, eps, mu, sig, oez, ohx, ohy, s_hyn);
    }
}

extern "C" void kernel_launch(void* const* d_in, const int* in_sizes, int n_in,
                              void* d_out, int out_size)
{
    const float* Ez  = (const float*)d_in[0];
    const float* Hx  = (const float*)d_in[1];
    const float* Hy  = (const float*)d_in[2];
    const float* eps = (const float*)d_in[3];
    const float* mu  = (const float*)d_in[4];
    const float* sig = (const float*)d_in[5];

    float* out = (float*)d_out;
    const int N = NX * NY;

    dim3 block(32, 8);                  // 8 warps, each owns a row pair
    dim3 grid(NY / 128, NX / TROWS);    // (32, 256)
    fdtd_pair_kernel<<<grid, block>>>(Ez, Hx, Hy, eps, mu, sig,
                                      out, out + N, out + 2 * N);
}